// round 2
// baseline (speedup 1.0000x reference)
#include <cuda_runtime.h>

// R2: weights-in-registers, k-packed f32x2, butterfly-reduced 2-layer LSTM.
// Grid 147 x 256 threads, 14 batch rows/CTA. Predicted ~1.0-1.3 ms.

typedef unsigned long long u64;

#define TT    512
#define NB    14
#define NTH   256
#define BTOT  2048
#define NCTA  ((BTOT + NB - 1) / NB)   // 147

__device__ __forceinline__ u64 pack2(float lo, float hi) {
    u64 r; asm("mov.b64 %0, {%1, %2};" : "=l"(r) : "f"(lo), "f"(hi)); return r;
}
__device__ __forceinline__ float2 unpack2(u64 a) {
    float2 r; asm("mov.b64 {%0, %1}, %2;" : "=f"(r.x), "=f"(r.y) : "l"(a)); return r;
}
__device__ __forceinline__ void fma2(u64 &d, u64 a, u64 b) {
    asm("fma.rn.f32x2 %0, %1, %2, %0;" : "+l"(d) : "l"(a), "l"(b));
}
__device__ __forceinline__ u64 add2(u64 a, u64 b) {
    u64 r; asm("add.rn.f32x2 %0, %1, %2;" : "=l"(r) : "l"(a), "l"(b)); return r;
}

__global__ __launch_bounds__(NTH, 1)
void lstm_fused(const float* __restrict__ x,
                const float* __restrict__ Wih1, const float* __restrict__ Whh1,
                const float* __restrict__ bih1, const float* __restrict__ bhh1,
                const float* __restrict__ Wih2, const float* __restrict__ Whh2,
                const float* __restrict__ bih2, const float* __restrict__ bhh2,
                const float* __restrict__ fc1w, const float* __restrict__ fc1b,
                const float* __restrict__ fc2w, const float* __restrict__ fc2b,
                float* __restrict__ out)
{
    // hcat row = [h1 (64) | h2 (32)]; double-buffered. L2(t) reads hcat[nxt]
    // (fresh h1_t + h2_{t-1}) and writes h2_t into hcat[cur] for step t+1.
    __shared__ __align__(16) float hcat[2][NB][96];
    __shared__ __align__(16) float xbuf[NB][4];
    __shared__ float sfc1w[512], sfc1b[16], sfc2w[16], sfc2b[1];

    const int tid  = threadIdx.x;
    const int role = tid & 3;        // L1 gate / L2 k-quarter & dance role
    const int jj   = tid >> 2;       // 0..63  (L1 hidden unit)
    const int j2   = tid >> 3;       // 0..31  (L2 hidden unit)
    const int bh   = (tid >> 2) & 1; // L2 batch half
    const int b0   = blockIdx.x * NB;
    const bool bvalid = (tid < NB) && (b0 + tid < BTOT);

    // ---- time-invariant weights -> registers (k-packed pairs) ----
    u64 w1[32], wxa, wxb, w2[4][12];
    float bias1, bias2;
    {
        int r1 = role * 64 + jj;
        const float2* Wp = (const float2*)(Whh1 + (size_t)r1 * 64);
        #pragma unroll
        for (int m = 0; m < 32; ++m) { float2 v = Wp[m]; w1[m] = pack2(v.x, v.y); }
        const float2* Xp = (const float2*)(Wih1 + (size_t)r1 * 4);
        { float2 v = Xp[0]; wxa = pack2(v.x, v.y); v = Xp[1]; wxb = pack2(v.x, v.y); }
        bias1 = bih1[r1] + bhh1[r1];
    }
    {
        #pragma unroll
        for (int gg = 0; gg < 4; ++gg) {
            int r2 = gg * 32 + j2;
            #pragma unroll
            for (int m = 0; m < 12; ++m) {
                int k = role * 24 + 2 * m;   // concat k: [0,64)=Wih2*h1, [64,96)=Whh2*h2
                float lo = (k < 64) ? Wih2[r2 * 64 + k]     : Whh2[r2 * 32 + (k - 64)];
                float hi = (k < 64) ? Wih2[r2 * 64 + k + 1] : Whh2[r2 * 32 + (k + 1 - 64)];
                w2[gg][m] = pack2(lo, hi);
            }
        }
        int r2r = role * 32 + j2;
        bias2 = bih2[r2r] + bhh2[r2r];
    }

    // activation constants: role==2 -> tanh, else sigmoid via 0.5*tanh(0.5x)+0.5
    const bool  isg  = (role == 2);
    const float k2c  = isg ? 2.f : 1.f;   // exp scale (tanh uses e^{2x}, sigma e^{x})
    const float amul = isg ? 1.f : 0.5f;
    const float aadd = isg ? 0.f : 0.5f;

    // ---- smem init ----
    for (int i2 = tid; i2 < 2 * NB * 96; i2 += NTH) ((float*)hcat)[i2] = 0.f;
    for (int i2 = tid; i2 < NB * 4;      i2 += NTH) ((float*)xbuf)[i2] = 0.f;
    for (int i2 = tid; i2 < 512;         i2 += NTH) sfc1w[i2] = fc1w[i2];
    if (tid < 16) sfc1b[tid] = fc1b[tid];
    if (tid < 16) sfc2w[tid] = fc2w[tid];
    if (tid == 0) sfc2b[0] = fc2b[0];
    __syncthreads();

    float c1loc[NB];
    #pragma unroll
    for (int i = 0; i < NB; ++i) c1loc[i] = 0.f;
    float c2loc[7];
    #pragma unroll
    for (int i = 0; i < 7; ++i) c2loc[i] = 0.f;

    float4 xreg = make_float4(0.f, 0.f, 0.f, 0.f);
    if (bvalid) xreg = *(const float4*)(x + (size_t)(b0 + tid) * TT * 4);

    int cur = 0;
    for (int t = 0; t < TT; ++t) {
        const int nxt = cur ^ 1;

        if (tid < NB) {
            *(float4*)&xbuf[tid][0] = xreg;
            if (bvalid && t + 1 < TT)
                xreg = *(const float4*)(x + ((size_t)(b0 + tid) * TT + t + 1) * 4);
        }
        __syncthreads();

        // ---------------- Layer 1: thread (jj, role=gate), full k ----------------
        #pragma unroll
        for (int b = 0; b < NB; ++b) {
            const ulonglong2* hb = (const ulonglong2*)&hcat[cur][b][0];
            const ulonglong2  xv = *(const ulonglong2*)&xbuf[b][0];
            u64 a0 = 0, a1 = 0, a2 = 0, a3 = 0;
            fma2(a0, wxa, xv.x);
            fma2(a1, wxb, xv.y);
            #pragma unroll
            for (int mm = 0; mm < 16; ++mm) {
                ulonglong2 hh = hb[mm];              // broadcast LDS.128
                if (mm & 1) { fma2(a2, w1[2*mm], hh.x); fma2(a3, w1[2*mm+1], hh.y); }
                else        { fma2(a0, w1[2*mm], hh.x); fma2(a1, w1[2*mm+1], hh.y); }
            }
            float2 ts  = unpack2(add2(add2(a0, a2), add2(a1, a3)));
            float  raw = ts.x + ts.y + bias1;

            float ev = __expf(k2c * raw);
            float th = 1.f - __fdividef(2.f, ev + 1.f);
            float a  = fmaf(amul, th, aadd);         // lane's activated gate
            float v2 = __shfl_xor_sync(0xffffffffu, a, 2);   // role1 gets o
            float p  = a * v2;                               // role0: i*g~
            float pv = __shfl_xor_sync(0xffffffffu, p, 1);   // role1 gets i*g~
            if (role == 1) {
                float cn = fmaf(a, c1loc[b], pv);            // f*c + i*g~
                c1loc[b] = cn;
                float e2 = __expf(2.f * cn);
                float tc = 1.f - __fdividef(2.f, e2 + 1.f);
                hcat[nxt][b][jj] = v2 * tc;                  // o * tanh(c)
            }
        }
        __syncthreads();

        // ------- Layer 2: thread (j2, bh, role=k-quarter), butterfly reduce -------
        #pragma unroll
        for (int i = 0; i < 7; ++i) {
            const int b = bh * 7 + i;
            const ulonglong2* hb =
                (const ulonglong2*)&hcat[nxt][b][0] + role * 6;  // 24-float quarter
            u64 ac0 = 0, ac1 = 0, ac2 = 0, ac3 = 0;
            #pragma unroll
            for (int mm = 0; mm < 6; ++mm) {
                ulonglong2 hh = hb[mm];
                fma2(ac0, w2[0][2*mm],   hh.x); fma2(ac1, w2[1][2*mm],   hh.x);
                fma2(ac2, w2[2][2*mm],   hh.x); fma2(ac3, w2[3][2*mm],   hh.x);
                fma2(ac0, w2[0][2*mm+1], hh.y); fma2(ac1, w2[1][2*mm+1], hh.y);
                fma2(ac2, w2[2][2*mm+1], hh.y); fma2(ac3, w2[3][2*mm+1], hh.y);
            }
            float2 f0 = unpack2(ac0), f1 = unpack2(ac1);
            float2 f2 = unpack2(ac2), f3 = unpack2(ac3);
            u64 A  = pack2(f0.x + f0.y, f1.x + f1.y);   // (i, f) partials
            u64 Bv = pack2(f2.x + f2.y, f3.x + f3.y);   // (g, o) partials
            A  = add2(A,  __shfl_xor_sync(0xffffffffu, A,  1));
            Bv = add2(Bv, __shfl_xor_sync(0xffffffffu, Bv, 1));
            A  = add2(A,  __shfl_xor_sync(0xffffffffu, A,  2));
            Bv = add2(Bv, __shfl_xor_sync(0xffffffffu, Bv, 2));
            float2 Af = unpack2(A), Bf = unpack2(Bv);
            float rlo = (role & 2) ? Bf.x : Af.x;
            float rhi = (role & 2) ? Bf.y : Af.y;
            float raw = ((role & 1) ? rhi : rlo) + bias2;

            float ev = __expf(k2c * raw);
            float th = 1.f - __fdividef(2.f, ev + 1.f);
            float a  = fmaf(amul, th, aadd);
            float v2 = __shfl_xor_sync(0xffffffffu, a, 2);
            float p  = a * v2;
            float pv = __shfl_xor_sync(0xffffffffu, p, 1);
            if (role == 1) {
                float cn = fmaf(a, c2loc[i], pv);
                c2loc[i] = cn;
                float e2 = __expf(2.f * cn);
                float tc = 1.f - __fdividef(2.f, e2 + 1.f);
                hcat[cur][b][64 + j2] = v2 * tc;   // h2_t for step t+1
            }
        }
        cur = nxt;
    }

    __syncthreads();

    // ---- FC head on final h2 ----
    if (bvalid) {
        const float* hv = &hcat[(TT - 1) & 1][tid][64];
        float o = sfc2b[0];
        #pragma unroll
        for (int f = 0; f < 16; ++f) {
            float acc = sfc1b[f];
            #pragma unroll
            for (int k = 0; k < 32; ++k)
                acc = fmaf(sfc1w[f * 32 + k], hv[k], acc);
            o = fmaf(sfc2w[f], fmaxf(acc, 0.f), o);
        }
        out[b0 + tid] = o;
    }
}

extern "C" void kernel_launch(void* const* d_in, const int* in_sizes, int n_in,
                              void* d_out, int out_size) {
    const float* x    = (const float*)d_in[0];
    const float* Wih1 = (const float*)d_in[1];
    const float* Whh1 = (const float*)d_in[2];
    const float* bih1 = (const float*)d_in[3];
    const float* bhh1 = (const float*)d_in[4];
    const float* Wih2 = (const float*)d_in[5];
    const float* Whh2 = (const float*)d_in[6];
    const float* bih2 = (const float*)d_in[7];
    const float* bhh2 = (const float*)d_in[8];
    const float* fc1w = (const float*)d_in[9];
    const float* fc1b = (const float*)d_in[10];
    const float* fc2w = (const float*)d_in[11];
    const float* fc2b = (const float*)d_in[12];
    float* out = (float*)d_out;

    lstm_fused<<<NCTA, NTH>>>(x, Wih1, Whh1, bih1, bhh1,
                              Wih2, Whh2, bih2, bhh2,
                              fc1w, fc1b, fc2w, fc2b, out);
}